// round 1
// baseline (speedup 1.0000x reference)
#include <cuda_runtime.h>
#include <math.h>

#define B_  16
#define L_  128
#define S_  64
#define T_  64
#define QD  1024
#define FD  1024
#define HD  512
#define OD  512
#define ST_ (S_*T_)

// ---------------- scratch (static device globals; no runtime alloc) ----------
__device__ float g_q  [B_*L_*HD];
__device__ float g_sk [B_*S_*HD];
__device__ float g_tk [B_*T_*HD];
__device__ float g_sv [B_*S_*HD];
__device__ float g_tv [B_*T_*HD];
__device__ float g_w  [(size_t)B_*L_*S_*T_];   // 33.5 MB
__device__ float g_rs [B_*L_];
__device__ float g_ctx[B_*L_*HD];

// ---------------- generic tiled SGEMM: C = A[MxK] @ W[KxN] + bias -----------
// BM=BN=64, BK=16, 256 threads, 4x4 micro-tile per thread
template<bool RELU>
__global__ void sgemm_bias(const float* __restrict__ A, const float* __restrict__ Wm,
                           const float* __restrict__ bias, float* __restrict__ C,
                           int M, int N, int K) {
    __shared__ __align__(16) float As[16][64];
    __shared__ __align__(16) float Bs[16][64];
    int tid = threadIdx.x;
    int tx = tid & 15, ty = tid >> 4;
    int bm = blockIdx.y * 64, bn = blockIdx.x * 64;
    float acc[4][4] = {};
    for (int k0 = 0; k0 < K; k0 += 16) {
        {   // A tile 64x16 (transposed into As[k][m])
            int r = tid >> 2, kc = (tid & 3) * 4;
            float4 v = *(const float4*)(A + (size_t)(bm + r) * K + k0 + kc);
            As[kc+0][r] = v.x; As[kc+1][r] = v.y; As[kc+2][r] = v.z; As[kc+3][r] = v.w;
        }
        {   // W tile 16x64
            int r = tid >> 4, c = (tid & 15) * 4;
            *(float4*)&Bs[r][c] = *(const float4*)(Wm + (size_t)(k0 + r) * N + bn + c);
        }
        __syncthreads();
        #pragma unroll
        for (int k = 0; k < 16; k++) {
            float4 a = *(const float4*)&As[k][ty*4];
            float4 b = *(const float4*)&Bs[k][tx*4];
            float ar[4] = {a.x,a.y,a.z,a.w};
            float br[4] = {b.x,b.y,b.z,b.w};
            #pragma unroll
            for (int i=0;i<4;i++)
                #pragma unroll
                for (int j=0;j<4;j++) acc[i][j] += ar[i]*br[j];
        }
        __syncthreads();
    }
    #pragma unroll
    for (int i=0;i<4;i++) {
        int m = bm + ty*4 + i;
        #pragma unroll
        for (int j=0;j<4;j++) {
            int n = bn + tx*4 + j;
            float v = acc[i][j] + bias[n];
            if (RELU) v = fmaxf(v, 0.f);
            C[(size_t)m*N + n] = v;
        }
    }
}

// ------- output GEMM with concat A = [A0 (K0) | A1 (K1)], + bias, relu ------
__global__ void sgemm_concat_relu(const float* __restrict__ A0, int K0,
                                  const float* __restrict__ A1, int K1,
                                  const float* __restrict__ Wm, const float* __restrict__ bias,
                                  float* __restrict__ C, int M, int N) {
    __shared__ __align__(16) float As[16][64];
    __shared__ __align__(16) float Bs[16][64];
    int tid = threadIdx.x;
    int tx = tid & 15, ty = tid >> 4;
    int bm = blockIdx.y * 64, bn = blockIdx.x * 64;
    int K = K0 + K1;
    float acc[4][4] = {};
    for (int k0 = 0; k0 < K; k0 += 16) {
        {
            int r = tid >> 2, kc = (tid & 3) * 4;
            const float* Ap; int kk, ld;
            if (k0 < K0) { Ap = A0; kk = k0; ld = K0; }
            else         { Ap = A1; kk = k0 - K0; ld = K1; }
            float4 v = *(const float4*)(Ap + (size_t)(bm + r) * ld + kk + kc);
            As[kc+0][r] = v.x; As[kc+1][r] = v.y; As[kc+2][r] = v.z; As[kc+3][r] = v.w;
        }
        {
            int r = tid >> 4, c = (tid & 15) * 4;
            *(float4*)&Bs[r][c] = *(const float4*)(Wm + (size_t)(k0 + r) * N + bn + c);
        }
        __syncthreads();
        #pragma unroll
        for (int k = 0; k < 16; k++) {
            float4 a = *(const float4*)&As[k][ty*4];
            float4 b = *(const float4*)&Bs[k][tx*4];
            float ar[4] = {a.x,a.y,a.z,a.w};
            float br[4] = {b.x,b.y,b.z,b.w};
            #pragma unroll
            for (int i=0;i<4;i++)
                #pragma unroll
                for (int j=0;j<4;j++) acc[i][j] += ar[i]*br[j];
        }
        __syncthreads();
    }
    #pragma unroll
    for (int i=0;i<4;i++) {
        int m = bm + ty*4 + i;
        #pragma unroll
        for (int j=0;j<4;j++) {
            int n = bn + tx*4 + j;
            float v = fmaxf(acc[i][j] + bias[n], 0.f);
            C[(size_t)m*N + n] = v;
        }
    }
}

// -------- trilinear logits: w[b,l,s,t] = (1/sqrt(HD)) * sum_k q*sk*tk -------
// block tile: 64 l x 16 s x 16 t. 256 threads, micro-tile 4x4x4 per thread.
__global__ void trilinear_kernel(const float* __restrict__ q, const float* __restrict__ sk,
                                 const float* __restrict__ tk, float* __restrict__ w) {
    __shared__ __align__(16) float qs [16][64];
    __shared__ __align__(16) float sks[16][16];
    __shared__ __align__(16) float tks[16][16];
    int tid  = threadIdx.x;
    int b    = blockIdx.z;
    int l0   = blockIdx.y * 64;
    int s0   = (blockIdx.x >> 2) * 16;
    int t0   = (blockIdx.x & 3) * 16;
    const float* qb  = q  + ((size_t)b*L_ + l0) * HD;
    const float* skb = sk + ((size_t)b*S_ + s0) * HD;
    const float* tkb = tk + ((size_t)b*T_ + t0) * HD;
    int ltid = tid & 15;
    int stid = (tid >> 4) & 3;
    int ttid = tid >> 6;
    float acc[4][4][4] = {};
    for (int k0 = 0; k0 < HD; k0 += 16) {
        {   int r = tid >> 2, kc = (tid & 3) * 4;
            float4 v = *(const float4*)(qb + (size_t)r*HD + k0 + kc);
            qs[kc+0][r]=v.x; qs[kc+1][r]=v.y; qs[kc+2][r]=v.z; qs[kc+3][r]=v.w;
        }
        if (tid < 64) {
            int r = tid >> 2, kc = (tid & 3) * 4;
            float4 v = *(const float4*)(skb + (size_t)r*HD + k0 + kc);
            sks[kc+0][r]=v.x; sks[kc+1][r]=v.y; sks[kc+2][r]=v.z; sks[kc+3][r]=v.w;
        } else if (tid < 128) {
            int u = tid - 64;
            int r = u >> 2, kc = (u & 3) * 4;
            float4 v = *(const float4*)(tkb + (size_t)r*HD + k0 + kc);
            tks[kc+0][r]=v.x; tks[kc+1][r]=v.y; tks[kc+2][r]=v.z; tks[kc+3][r]=v.w;
        }
        __syncthreads();
        #pragma unroll
        for (int k = 0; k < 16; k++) {
            float4 a4 = *(const float4*)&qs [k][ltid*4];
            float4 s4 = *(const float4*)&sks[k][stid*4];
            float4 t4 = *(const float4*)&tks[k][ttid*4];
            float aq[4] = {a4.x,a4.y,a4.z,a4.w};
            float as[4] = {s4.x,s4.y,s4.z,s4.w};
            float at[4] = {t4.x,t4.y,t4.z,t4.w};
            #pragma unroll
            for (int j=0;j<4;j++) {
                #pragma unroll
                for (int m=0;m<4;m++) {
                    float p = as[j] * at[m];
                    #pragma unroll
                    for (int i=0;i<4;i++) acc[i][j][m] += aq[i]*p;
                }
            }
        }
        __syncthreads();
    }
    const float scale = 0.044194173824159216f;  // 1/sqrt(512)
    #pragma unroll
    for (int i=0;i<4;i++) {
        int l = l0 + ltid*4 + i;
        #pragma unroll
        for (int j=0;j<4;j++) {
            int s = s0 + stid*4 + j;
            float4 v = make_float4(acc[i][j][0]*scale, acc[i][j][1]*scale,
                                   acc[i][j][2]*scale, acc[i][j][3]*scale);
            *(float4*)(w + (((size_t)b*L_ + l)*S_ + s)*T_ + t0 + ttid*4) = v;
        }
    }
}

// ------------- joint softmax over st=4096 per (b,l); stores exp + rowsum ----
__global__ void softmax_kernel(float* __restrict__ w, float* __restrict__ rowsum) {
    int row = blockIdx.x;                       // b*L + l
    float4* p4 = (float4*)(w + (size_t)row * ST_);
    int tid = threadIdx.x;                      // 256
    float4 v[4];
    float mx = -1e30f;
    #pragma unroll
    for (int i = 0; i < 4; i++) {
        v[i] = p4[tid + i*256];
        mx = fmaxf(mx, fmaxf(fmaxf(v[i].x, v[i].y), fmaxf(v[i].z, v[i].w)));
    }
    __shared__ float red[256];
    red[tid] = mx; __syncthreads();
    #pragma unroll
    for (int s = 128; s > 0; s >>= 1) {
        if (tid < s) red[tid] = fmaxf(red[tid], red[tid+s]);
        __syncthreads();
    }
    mx = red[0];
    __syncthreads();
    float sum = 0.f;
    #pragma unroll
    for (int i = 0; i < 4; i++) {
        float4 e;
        e.x = expf(v[i].x - mx); e.y = expf(v[i].y - mx);
        e.z = expf(v[i].z - mx); e.w = expf(v[i].w - mx);
        sum += (e.x + e.y) + (e.z + e.w);
        p4[tid + i*256] = e;
    }
    red[tid] = sum; __syncthreads();
    #pragma unroll
    for (int s = 128; s > 0; s >>= 1) {
        if (tid < s) red[tid] += red[tid+s];
        __syncthreads();
    }
    if (tid == 0) rowsum[row] = red[0];
}

// -- ctx[b,l,k] = (1/Z) sum_st e[l,st] * sv[s,k]*tv[t,k]  (per-batch GEMM) ---
// block: 64 l x 64 k, K-dim = st (4096) in chunks of 16 (single s per chunk)
__global__ void ctx_kernel(const float* __restrict__ w, const float* __restrict__ sv,
                           const float* __restrict__ tv, const float* __restrict__ rowsum,
                           float* __restrict__ ctx) {
    __shared__ __align__(16) float ws [16][64];   // [st][l]
    __shared__ __align__(16) float svs[64];       // current s row (k tile)
    __shared__ __align__(16) float tvs[16][64];   // [t][k]
    int tid = threadIdx.x;
    int tx = tid & 15, ty = tid >> 4;
    int b  = blockIdx.z, l0 = blockIdx.y * 64, n0 = blockIdx.x * 64;
    const float* wb  = w  + ((size_t)b*L_ + l0) * ST_;
    const float* svb = sv + (size_t)b*S_*HD + n0;
    const float* tvb = tv + (size_t)b*T_*HD + n0;
    float acc[4][4] = {};
    for (int st0 = 0; st0 < ST_; st0 += 16) {
        int s     = st0 >> 6;
        int tbase = st0 & 63;
        {   int r = tid >> 2, c = (tid & 3) * 4;
            float4 v = *(const float4*)(wb + (size_t)r*ST_ + st0 + c);
            ws[c+0][r]=v.x; ws[c+1][r]=v.y; ws[c+2][r]=v.z; ws[c+3][r]=v.w;
        }
        {   int r = tid >> 4, c = (tid & 15) * 4;
            *(float4*)&tvs[r][c] = *(const float4*)(tvb + (size_t)(tbase + r)*HD + c);
        }
        if (tid < 16)
            *(float4*)&svs[tid*4] = *(const float4*)(svb + (size_t)s*HD + tid*4);
        __syncthreads();
        float4 sv4 = *(const float4*)&svs[tx*4];
        float svr[4] = {sv4.x, sv4.y, sv4.z, sv4.w};
        #pragma unroll
        for (int kk = 0; kk < 16; kk++) {
            float4 a4 = *(const float4*)&ws [kk][ty*4];
            float4 t4 = *(const float4*)&tvs[kk][tx*4];
            float ar[4] = {a4.x,a4.y,a4.z,a4.w};
            float bb[4];
            bb[0] = svr[0]*t4.x; bb[1] = svr[1]*t4.y;
            bb[2] = svr[2]*t4.z; bb[3] = svr[3]*t4.w;
            #pragma unroll
            for (int i=0;i<4;i++)
                #pragma unroll
                for (int j=0;j<4;j++) acc[i][j] += ar[i]*bb[j];
        }
        __syncthreads();
    }
    #pragma unroll
    for (int i=0;i<4;i++) {
        int l = l0 + ty*4 + i;
        float inv = 1.f / rowsum[b*L_ + l];
        #pragma unroll
        for (int j=0;j<4;j++) {
            int n = n0 + tx*4 + j;
            ctx[((size_t)b*L_ + l)*HD + n] = acc[i][j] * inv;
        }
    }
}

// ----------------------------------------------------------------------------
extern "C" void kernel_launch(void* const* d_in, const int* in_sizes, int n_in,
                              void* d_out, int out_size) {
    const float* query = (const float*)d_in[0];
    const float* src   = (const float*)d_in[1];
    const float* trg   = (const float*)d_in[2];
    const float* Wq    = (const float*)d_in[3];
    const float* bq    = (const float*)d_in[4];
    const float* Ws    = (const float*)d_in[5];
    const float* bs    = (const float*)d_in[6];
    const float* Wt    = (const float*)d_in[7];
    const float* bt    = (const float*)d_in[8];
    const float* Wsv   = (const float*)d_in[9];
    const float* bsv   = (const float*)d_in[10];
    const float* Wtv   = (const float*)d_in[11];
    const float* btv   = (const float*)d_in[12];
    const float* Wo    = (const float*)d_in[13];
    const float* bo    = (const float*)d_in[14];
    float* out = (float*)d_out;

    float *gq, *gsk, *gtk, *gsv, *gtv, *gw, *grs, *gctx;
    cudaGetSymbolAddress((void**)&gq,  g_q);
    cudaGetSymbolAddress((void**)&gsk, g_sk);
    cudaGetSymbolAddress((void**)&gtk, g_tk);
    cudaGetSymbolAddress((void**)&gsv, g_sv);
    cudaGetSymbolAddress((void**)&gtv, g_tv);
    cudaGetSymbolAddress((void**)&gw,  g_w);
    cudaGetSymbolAddress((void**)&grs, g_rs);
    cudaGetSymbolAddress((void**)&gctx,g_ctx);

    dim3 blk(256);
    // projections
    sgemm_bias<false><<<dim3(HD/64, (B_*L_)/64), blk>>>(query, Wq,  bq,  gq,  B_*L_, HD, QD);
    sgemm_bias<false><<<dim3(HD/64, (B_*S_)/64), blk>>>(src,   Ws,  bs,  gsk, B_*S_, HD, FD);
    sgemm_bias<false><<<dim3(HD/64, (B_*T_)/64), blk>>>(trg,   Wt,  bt,  gtk, B_*T_, HD, FD);
    sgemm_bias<false><<<dim3(HD/64, (B_*S_)/64), blk>>>(src,   Wsv, bsv, gsv, B_*S_, HD, FD);
    sgemm_bias<false><<<dim3(HD/64, (B_*T_)/64), blk>>>(trg,   Wtv, btv, gtv, B_*T_, HD, FD);
    // trilinear logits
    trilinear_kernel<<<dim3(16, 2, B_), blk>>>(gq, gsk, gtk, gw);
    // joint softmax over (s,t)
    softmax_kernel<<<B_*L_, blk>>>(gw, grs);
    // context
    ctx_kernel<<<dim3(HD/64, 2, B_), blk>>>(gw, gsv, gtv, grs, gctx);
    // output: relu(concat(query, ctx) @ Wo + bo)
    sgemm_concat_relu<<<dim3(OD/64, (B_*L_)/64), blk>>>(query, QD, gctx, HD,
                                                        Wo, bo, out, B_*L_, OD);
}

// round 2
// speedup vs baseline: 1.4863x; 1.4863x over previous
#include <cuda_runtime.h>
#include <math.h>

#define B_  16
#define L_  128
#define S_  64
#define T_  64
#define QD  1024
#define FD  1024
#define HD  512
#define OD  512
#define ST_ 4096

typedef unsigned long long u64;

// ---------------- scratch (static device globals) ---------------------------
__device__ float g_q  [B_*L_*HD];
__device__ float g_sk [B_*S_*HD];
__device__ float g_tk [B_*T_*HD];
__device__ float g_sv [B_*S_*HD];
__device__ float g_tv [B_*T_*HD];
__device__ float g_w  [(size_t)B_*L_*ST_];     // 33.5 MB
__device__ float g_rs [B_*L_];
__device__ float g_ctx[B_*L_*HD];
__device__ float g_part[64*128*512];           // split-K scratch (16.8 MB)

// ---------------- packed f32x2 helpers --------------------------------------
__device__ __forceinline__ u64 pk2(float x, float y){
    u64 r; asm("mov.b64 %0,{%1,%2};":"=l"(r):"f"(x),"f"(y)); return r;
}
__device__ __forceinline__ void fma2(u64 &c, u64 a, u64 b){
    asm("fma.rn.f32x2 %0,%1,%2,%0;":"+l"(c):"l"(a),"l"(b));
}
__device__ __forceinline__ u64 mul2(u64 a, u64 b){
    u64 d; asm("mul.rn.f32x2 %0,%1,%2;":"=l"(d):"l"(a),"l"(b)); return d;
}
__device__ __forceinline__ float2 upk2(u64 v){
    float lo,hi; asm("mov.b64 {%0,%1},%2;":"=f"(lo),"=f"(hi):"l"(v));
    return make_float2(lo,hi);
}

// 8 rows x 4 col-pairs micro-step: acc[i][p] += dup(a_i) * bp[p]
__device__ __forceinline__ void mma_step(u64 acc[8][4], float4 a0, float4 a1, const u64 bp[4]){
    u64 ad[8];
    ad[0]=pk2(a0.x,a0.x); ad[1]=pk2(a0.y,a0.y); ad[2]=pk2(a0.z,a0.z); ad[3]=pk2(a0.w,a0.w);
    ad[4]=pk2(a1.x,a1.x); ad[5]=pk2(a1.y,a1.y); ad[6]=pk2(a1.z,a1.z); ad[7]=pk2(a1.w,a1.w);
    #pragma unroll
    for (int i=0;i<8;i++)
        #pragma unroll
        for (int p=0;p<4;p++) fma2(acc[i][p], ad[i], bp[p]);
}

// ======================= merged projection GEMMs ============================
// C = A[Mx1024] @ W[1024x512] + bias ; 5 tasks packed into one grid.
struct ProjArgs {
    const float* A[5];
    const float* W[5];
    const float* bias[5];
    float*       C[5];
};

__global__ __launch_bounds__(256,2) void proj_kernel(ProjArgs args){
    __shared__ __align__(16) float As[2][8][128];
    __shared__ __align__(16) float Bs[2][8][128];
    int tid = threadIdx.x, tx = tid&15, ty = tid>>4;
    int y = blockIdx.y;
    int task, mt;
    if (y < 16){ task=0; mt=y; } else { task = 1 + ((y-16)>>3); mt = (y-16)&7; }
    const float* A    = args.A[task];
    const float* Wm   = args.W[task];
    const float* bias = args.bias[task];
    float*       C    = args.C[task];
    int bm = mt*128, bn = blockIdx.x*128;
    const int K = 1024;

    int ar = tid>>1, akc = (tid&1)*4;      // A staging: row, k-offset (1 float4/thread)
    int br = tid>>5, bc = (tid&31)*4;      // B staging: k-row, n-col
    const float* Ap = A  + (size_t)(bm+ar)*K + akc;
    const float* Bp = Wm + (size_t)br*OD + bn + bc;

    float4 ra = *(const float4*)Ap;
    float4 rb = *(const float4*)Bp;
    {   float av[4]={ra.x,ra.y,ra.z,ra.w};
        #pragma unroll
        for(int i=0;i<4;i++){ int k=akc+i; As[0][k][ar ^ (k<<2)] = av[i]; }
        *(float4*)&Bs[0][br][bc] = rb;
    }
    __syncthreads();

    u64 acc[8][4];
    #pragma unroll
    for(int i=0;i<8;i++)
        #pragma unroll
        for(int p=0;p<4;p++) acc[i][p]=0ull;

    const int nt = K/8;
    for (int kt=0; kt<nt; kt++){
        int cur = kt&1;
        if (kt+1 < nt){
            ra = *(const float4*)(Ap + (kt+1)*8);
            rb = *(const float4*)(Bp + (size_t)(kt+1)*8*OD);
        }
        #pragma unroll
        for (int k=0;k<8;k++){
            int sc = k<<2;
            float4 a0 = *(const float4*)&As[cur][k][(ty*4)^sc];
            float4 a1 = *(const float4*)&As[cur][k][(64+ty*4)^sc];
            ulonglong2 b0 = *(const ulonglong2*)&Bs[cur][k][tx*4];
            ulonglong2 b1 = *(const ulonglong2*)&Bs[cur][k][64+tx*4];
            u64 bp[4] = { b0.x, b0.y, b1.x, b1.y };
            mma_step(acc, a0, a1, bp);
        }
        if (kt+1 < nt){
            int nxt = cur^1;
            float av[4]={ra.x,ra.y,ra.z,ra.w};
            #pragma unroll
            for(int i=0;i<4;i++){ int k=akc+i; As[nxt][k][ar ^ (k<<2)] = av[i]; }
            *(float4*)&Bs[nxt][br][bc] = rb;
        }
        __syncthreads();
    }
    #pragma unroll
    for (int i=0;i<8;i++){
        int m = bm + ((i<4)? ty*4+i : 64+ty*4+(i-4));
        #pragma unroll
        for (int h=0; h<2; h++){
            int n = bn + h*64 + tx*4;
            float2 u0 = upk2(acc[i][h*2+0]);
            float2 u1 = upk2(acc[i][h*2+1]);
            float4 o = make_float4(u0.x+bias[n], u0.y+bias[n+1], u1.x+bias[n+2], u1.y+bias[n+3]);
            *(float4*)(C + (size_t)m*OD + n) = o;
        }
    }
}

// ============ trilinear logits: w[l, st] = q @ (sk ⊙ tk)^T / sqrt(HD) =======
// per block: b fixed, all 128 l, N-tile = 2 s x 64 t = 128 st cols, K=512.
__global__ __launch_bounds__(256,2) void tri_kernel(const float* __restrict__ q,
        const float* __restrict__ sk, const float* __restrict__ tk, float* __restrict__ w){
    __shared__ __align__(16) float Qs[2][8][128];
    __shared__ __align__(16) float Ts[2][8][64];
    __shared__ __align__(16) float Ss[2][8][2];
    int tid=threadIdx.x, tx=tid&15, ty=tid>>4;
    int b = blockIdx.z;
    int s0 = blockIdx.x*2;
    const float* qb  = q  + (size_t)b*L_*HD;
    const float* tkb = tk + (size_t)b*T_*HD;
    const float* skb = sk + (size_t)(b*S_ + s0)*HD;

    int ar = tid>>1, akc=(tid&1)*4;
    const float* Ap = qb + (size_t)ar*HD + akc;
    const float* Tp = tkb + (size_t)(tid>>1)*HD + (tid&1)*4;   // valid for tid<128 (rows 0..63)
    int sidx = (tid-128)>>3, skk=(tid-128)&7;
    const float* Sp = skb + (size_t)sidx*HD + skk;             // valid for 128<=tid<144

    float4 ra = *(const float4*)Ap;
    float4 rt = make_float4(0,0,0,0); float rs = 0.f;
    if (tid<128) rt = *(const float4*)Tp;
    if (tid>=128 && tid<144) rs = *Sp;
    {   float av[4]={ra.x,ra.y,ra.z,ra.w};
        #pragma unroll
        for(int i=0;i<4;i++){ int k=akc+i; Qs[0][k][ar ^ (k<<2)] = av[i]; }
        if (tid<128){
            float tv_[4]={rt.x,rt.y,rt.z,rt.w};
            int r=tid>>1, kc=(tid&1)*4;
            #pragma unroll
            for(int i=0;i<4;i++){ int k=kc+i; Ts[0][k][r ^ (k<<2)] = tv_[i]; }
        }
        if (tid>=128 && tid<144) Ss[0][skk][sidx] = rs;
    }
    __syncthreads();

    u64 acc[8][4];
    #pragma unroll
    for(int i=0;i<8;i++)
        #pragma unroll
        for(int p=0;p<4;p++) acc[i][p]=0ull;

    const int nt = HD/8;   // 64
    for (int kt=0; kt<nt; kt++){
        int cur = kt&1;
        if (kt+1 < nt){
            ra = *(const float4*)(Ap + (kt+1)*8);
            if (tid<128) rt = *(const float4*)(Tp + (kt+1)*8);
            if (tid>=128 && tid<144) rs = *(Sp + (kt+1)*8);
        }
        #pragma unroll
        for (int k=0;k<8;k++){
            int sc = k<<2;
            float4 a0 = *(const float4*)&Qs[cur][k][(ty*4)^sc];
            float4 a1 = *(const float4*)&Qs[cur][k][(64+ty*4)^sc];
            ulonglong2 tp = *(const ulonglong2*)&Ts[cur][k][(tx*4)^sc];
            float s0v = Ss[cur][k][0], s1v = Ss[cur][k][1];
            u64 s0d = pk2(s0v,s0v), s1d = pk2(s1v,s1v);
            u64 bp[4] = { mul2(s0d,tp.x), mul2(s0d,tp.y), mul2(s1d,tp.x), mul2(s1d,tp.y) };
            mma_step(acc, a0, a1, bp);
        }
        if (kt+1 < nt){
            int nxt = cur^1;
            float av[4]={ra.x,ra.y,ra.z,ra.w};
            #pragma unroll
            for(int i=0;i<4;i++){ int k=akc+i; Qs[nxt][k][ar ^ (k<<2)] = av[i]; }
            if (tid<128){
                float tv_[4]={rt.x,rt.y,rt.z,rt.w};
                int r=tid>>1, kc=(tid&1)*4;
                #pragma unroll
                for(int i=0;i<4;i++){ int k=kc+i; Ts[nxt][k][r ^ (k<<2)] = tv_[i]; }
            }
            if (tid>=128 && tid<144) Ss[nxt][skk][sidx] = rs;
        }
        __syncthreads();
    }
    const float scale = 0.044194173824159216f;  // 1/sqrt(512)
    #pragma unroll
    for (int i=0;i<8;i++){
        int m = ((i<4)? ty*4+i : 64+ty*4+(i-4));
        float* wr = w + ((size_t)(b*L_+m))*ST_ + blockIdx.x*128;
        #pragma unroll
        for (int h=0; h<2; h++){
            float2 u0 = upk2(acc[i][h*2+0]);
            float2 u1 = upk2(acc[i][h*2+1]);
            float4 o = make_float4(u0.x*scale, u0.y*scale, u1.x*scale, u1.y*scale);
            *(float4*)(wr + h*64 + tx*4) = o;
        }
    }
}

// ----------- joint softmax over st=4096; stores exp in place + rowsum -------
__global__ void softmax_kernel(float* __restrict__ w, float* __restrict__ rowsum) {
    int row = blockIdx.x;
    float4* p4 = (float4*)(w + (size_t)row * ST_);
    int tid = threadIdx.x;
    float4 v[4];
    float mx = -1e30f;
    #pragma unroll
    for (int i = 0; i < 4; i++) {
        v[i] = p4[tid + i*256];
        mx = fmaxf(mx, fmaxf(fmaxf(v[i].x, v[i].y), fmaxf(v[i].z, v[i].w)));
    }
    __shared__ float red[256];
    red[tid] = mx; __syncthreads();
    #pragma unroll
    for (int s = 128; s > 0; s >>= 1) {
        if (tid < s) red[tid] = fmaxf(red[tid], red[tid+s]);
        __syncthreads();
    }
    mx = red[0];
    __syncthreads();
    float sum = 0.f;
    #pragma unroll
    for (int i = 0; i < 4; i++) {
        float4 e;
        e.x = expf(v[i].x - mx); e.y = expf(v[i].y - mx);
        e.z = expf(v[i].z - mx); e.w = expf(v[i].w - mx);
        sum += (e.x + e.y) + (e.z + e.w);
        p4[tid + i*256] = e;
    }
    red[tid] = sum; __syncthreads();
    #pragma unroll
    for (int s = 128; s > 0; s >>= 1) {
        if (tid < s) red[tid] += red[tid+s];
        __syncthreads();
    }
    if (tid == 0) rowsum[row] = red[0];
}

// ====== ctx partial: part[z, l, n] = E[l, st-range] @ (sv ⊙ tv)[st, n] ======
// z = b*4 + split; split covers 1024 st values. N-tile 128 of 512.
__global__ __launch_bounds__(256,2) void ctx_kernel(const float* __restrict__ E,
        const float* __restrict__ sv, const float* __restrict__ tv, float* __restrict__ part){
    __shared__ __align__(16) float As[2][8][128];
    __shared__ __align__(16) float Bs[2][8][128];
    int tid=threadIdx.x, tx=tid&15, ty=tid>>4;
    int z = blockIdx.z; int b = z>>2, sp = z&3;
    int bn = blockIdx.x*128;
    int st_base = sp*1024;
    const float* Eb  = E  + (size_t)b*L_*ST_;
    const float* svb = sv + (size_t)b*S_*HD + bn;
    const float* tvb = tv + (size_t)b*T_*HD + bn;
    int ar=tid>>1, akc=(tid&1)*4;
    int br=tid>>5, bc=(tid&31)*4;

    float4 ra, rb;
    {   ra = *(const float4*)(Eb + (size_t)ar*ST_ + st_base + akc);
        int st = st_base + br; int s=st>>6, t=st&63;
        float4 t4 = *(const float4*)(tvb + (size_t)t*HD + bc);
        float4 s4 = *(const float4*)(svb + (size_t)s*HD + bc);
        rb = make_float4(t4.x*s4.x, t4.y*s4.y, t4.z*s4.z, t4.w*s4.w);
    }
    {   float av[4]={ra.x,ra.y,ra.z,ra.w};
        #pragma unroll
        for(int i=0;i<4;i++){ int k=akc+i; As[0][k][ar ^ (k<<2)] = av[i]; }
        *(float4*)&Bs[0][br][bc] = rb;
    }
    __syncthreads();

    u64 acc[8][4];
    #pragma unroll
    for(int i=0;i<8;i++)
        #pragma unroll
        for(int p=0;p<4;p++) acc[i][p]=0ull;

    const int nt = 1024/8;   // 128
    for (int kt=0; kt<nt; kt++){
        int cur = kt&1;
        if (kt+1 < nt){
            int st0 = st_base + (kt+1)*8;
            ra = *(const float4*)(Eb + (size_t)ar*ST_ + st0 + akc);
            int st = st0 + br; int s=st>>6, t=st&63;
            float4 t4 = *(const float4*)(tvb + (size_t)t*HD + bc);
            float4 s4 = *(const float4*)(svb + (size_t)s*HD + bc);
            rb = make_float4(t4.x*s4.x, t4.y*s4.y, t4.z*s4.z, t4.w*s4.w);
        }
        #pragma unroll
        for (int k=0;k<8;k++){
            int sc = k<<2;
            float4 a0 = *(const float4*)&As[cur][k][(ty*4)^sc];
            float4 a1 = *(const float4*)&As[cur][k][(64+ty*4)^sc];
            ulonglong2 b0 = *(const ulonglong2*)&Bs[cur][k][tx*4];
            ulonglong2 b1 = *(const ulonglong2*)&Bs[cur][k][64+tx*4];
            u64 bp[4] = { b0.x, b0.y, b1.x, b1.y };
            mma_step(acc, a0, a1, bp);
        }
        if (kt+1 < nt){
            int nxt = cur^1;
            float av[4]={ra.x,ra.y,ra.z,ra.w};
            #pragma unroll
            for(int i=0;i<4;i++){ int k=akc+i; As[nxt][k][ar ^ (k<<2)] = av[i]; }
            *(float4*)&Bs[nxt][br][bc] = rb;
        }
        __syncthreads();
    }
    #pragma unroll
    for (int i=0;i<8;i++){
        int m = ((i<4)? ty*4+i : 64+ty*4+(i-4));
        #pragma unroll
        for (int h=0; h<2; h++){
            float2 u0 = upk2(acc[i][h*2+0]);
            float2 u1 = upk2(acc[i][h*2+1]);
            float4 o = make_float4(u0.x, u0.y, u1.x, u1.y);
            *(float4*)(part + ((size_t)z*128 + m)*512 + bn + h*64 + tx*4) = o;
        }
    }
}

// reduce the 4 split-K partials, apply 1/rowsum
__global__ void ctx_reduce(const float* __restrict__ part, const float* __restrict__ rs,
                           float* __restrict__ ctx){
    int gid = blockIdx.x*256 + threadIdx.x;       // float4 id over 16*128*128
    int n4 = gid & 127; int rest = gid >> 7; int l = rest & 127; int b = rest >> 7;
    const float4* p = (const float4*)part;
    float4 a = make_float4(0,0,0,0);
    #pragma unroll
    for (int sp=0; sp<4; sp++){
        float4 v = p[ ((size_t)(b*4+sp)*128 + l)*128 + n4 ];
        a.x+=v.x; a.y+=v.y; a.z+=v.z; a.w+=v.w;
    }
    float inv = 1.f / rs[b*128 + l];
    ((float4*)ctx)[gid] = make_float4(a.x*inv, a.y*inv, a.z*inv, a.w*inv);
}

// ===== out partial: part[sp, m, n] = concat(query,ctx)[m, k-range] @ Wo =====
__global__ __launch_bounds__(256,2) void out_kernel(const float* __restrict__ query,
        const float* __restrict__ ctx, const float* __restrict__ Wo, float* __restrict__ part){
    __shared__ __align__(16) float As[2][8][128];
    __shared__ __align__(16) float Bs[2][8][128];
    int tid=threadIdx.x, tx=tid&15, ty=tid>>4;
    int bm = blockIdx.y*128, bn = blockIdx.x*128;
    int sp = blockIdx.z; int k_base = sp*768;
    int ar=tid>>1, akc=(tid&1)*4;
    int br=tid>>5, bc=(tid&31)*4;

    float4 ra, rb;
    {   int k = k_base + akc;
        ra = (k < 1024) ? *(const float4*)(query + (size_t)(bm+ar)*QD + k)
                        : *(const float4*)(ctx   + (size_t)(bm+ar)*HD + (k-1024));
        rb = *(const float4*)(Wo + (size_t)(k_base+br)*OD + bn + bc);
    }
    {   float av[4]={ra.x,ra.y,ra.z,ra.w};
        #pragma unroll
        for(int i=0;i<4;i++){ int k=akc+i; As[0][k][ar ^ (k<<2)] = av[i]; }
        *(float4*)&Bs[0][br][bc] = rb;
    }
    __syncthreads();

    u64 acc[8][4];
    #pragma unroll
    for(int i=0;i<8;i++)
        #pragma unroll
        for(int p=0;p<4;p++) acc[i][p]=0ull;

    const int nt = 768/8;   // 96
    for (int kt=0; kt<nt; kt++){
        int cur = kt&1;
        if (kt+1 < nt){
            int k = k_base + (kt+1)*8 + akc;
            ra = (k < 1024) ? *(const float4*)(query + (size_t)(bm+ar)*QD + k)
                            : *(const float4*)(ctx   + (size_t)(bm+ar)*HD + (k-1024));
            rb = *(const float4*)(Wo + (size_t)(k_base+(kt+1)*8+br)*OD + bn + bc);
        }
        #pragma unroll
        for (int k=0;k<8;k++){
            int sc = k<<2;
            float4 a0 = *(const float4*)&As[cur][k][(ty*4)^sc];
            float4 a1 = *(const float4*)&As[cur][k][(64+ty*4)^sc];
            ulonglong2 b0 = *(const ulonglong2*)&Bs[cur][k][tx*4];
            ulonglong2 b1 = *(const ulonglong2*)&Bs[cur][k][64+tx*4];
            u64 bp[4] = { b0.x, b0.y, b1.x, b1.y };
            mma_step(acc, a0, a1, bp);
        }
        if (kt+1 < nt){
            int nxt = cur^1;
            float av[4]={ra.x,ra.y,ra.z,ra.w};
            #pragma unroll
            for(int i=0;i<4;i++){ int k=akc+i; As[nxt][k][ar ^ (k<<2)] = av[i]; }
            *(float4*)&Bs[nxt][br][bc] = rb;
        }
        __syncthreads();
    }
    #pragma unroll
    for (int i=0;i<8;i++){
        int m = bm + ((i<4)? ty*4+i : 64+ty*4+(i-4));
        #pragma unroll
        for (int h=0; h<2; h++){
            float2 u0 = upk2(acc[i][h*2+0]);
            float2 u1 = upk2(acc[i][h*2+1]);
            float4 o = make_float4(u0.x, u0.y, u1.x, u1.y);
            *(float4*)(part + ((size_t)sp*2048 + m)*512 + bn + h*64 + tx*4) = o;
        }
    }
}

// reduce 2 split-K partials + bias + relu
__global__ void out_reduce(const float* __restrict__ part, const float* __restrict__ bo,
                           float* __restrict__ out){
    int gid = blockIdx.x*256 + threadIdx.x;       // float4 id over 2048*128
    int n4 = gid & 127; int m = gid >> 7;
    float4 p0 = ((const float4*)part)[(size_t)m*128 + n4];
    float4 p1 = ((const float4*)part)[(size_t)(2048+m)*128 + n4];
    float4 bb = ((const float4*)bo)[n4];
    float4 o = make_float4(fmaxf(p0.x+p1.x+bb.x, 0.f), fmaxf(p0.y+p1.y+bb.y, 0.f),
                           fmaxf(p0.z+p1.z+bb.z, 0.f), fmaxf(p0.w+p1.w+bb.w, 0.f));
    ((float4*)out)[gid] = o;
}

// ----------------------------------------------------------------------------
extern "C" void kernel_launch(void* const* d_in, const int* in_sizes, int n_in,
                              void* d_out, int out_size) {
    const float* query = (const float*)d_in[0];
    const float* src   = (const float*)d_in[1];
    const float* trg   = (const float*)d_in[2];
    const float* Wq    = (const float*)d_in[3];
    const float* bq    = (const float*)d_in[4];
    const float* Ws    = (const float*)d_in[5];
    const float* bs    = (const float*)d_in[6];
    const float* Wt    = (const float*)d_in[7];
    const float* bt    = (const float*)d_in[8];
    const float* Wsv   = (const float*)d_in[9];
    const float* bsv   = (const float*)d_in[10];
    const float* Wtv   = (const float*)d_in[11];
    const float* btv   = (const float*)d_in[12];
    const float* Wo    = (const float*)d_in[13];
    const float* bo    = (const float*)d_in[14];
    float* out = (float*)d_out;

    float *gq, *gsk, *gtk, *gsv, *gtv, *gw, *grs, *gctx, *gpart;
    cudaGetSymbolAddress((void**)&gq,   g_q);
    cudaGetSymbolAddress((void**)&gsk,  g_sk);
    cudaGetSymbolAddress((void**)&gtk,  g_tk);
    cudaGetSymbolAddress((void**)&gsv,  g_sv);
    cudaGetSymbolAddress((void**)&gtv,  g_tv);
    cudaGetSymbolAddress((void**)&gw,   g_w);
    cudaGetSymbolAddress((void**)&grs,  g_rs);
    cudaGetSymbolAddress((void**)&gctx, g_ctx);
    cudaGetSymbolAddress((void**)&gpart,g_part);

    ProjArgs pa;
    pa.A[0]=query; pa.A[1]=src; pa.A[2]=trg; pa.A[3]=src; pa.A[4]=trg;
    pa.W[0]=Wq;    pa.W[1]=Ws;  pa.W[2]=Wt;  pa.W[3]=Wsv; pa.W[4]=Wtv;
    pa.bias[0]=bq; pa.bias[1]=bs; pa.bias[2]=bt; pa.bias[3]=bsv; pa.bias[4]=btv;
    pa.C[0]=gq;    pa.C[1]=gsk; pa.C[2]=gtk; pa.C[3]=gsv; pa.C[4]=gtv;

    proj_kernel   <<<dim3(4,48),   256>>>(pa);
    tri_kernel    <<<dim3(32,1,16),256>>>(gq, gsk, gtk, gw);
    softmax_kernel<<<B_*L_,        256>>>(gw, grs);
    ctx_kernel    <<<dim3(4,1,64), 256>>>(gw, gsv, gtv, gpart);
    ctx_reduce    <<<1024,         256>>>(gpart, grs, gctx);
    out_kernel    <<<dim3(4,16,2), 256>>>(query, gctx, Wo, gpart);
    out_reduce    <<<1024,         256>>>(gpart, bo, out);
}

// round 4
// speedup vs baseline: 2.2212x; 1.4944x over previous
#include <cuda_runtime.h>
#include <math.h>

#define B_  16
#define L_  128
#define S_  64
#define T_  64
#define QD  1024
#define HD  512
#define OD  512
#define ST_ 4096

typedef unsigned long long u64;
typedef unsigned int u32;

// ---------------- scratch (static device globals) ---------------------------
__device__ float g_q  [B_*L_*HD];
__device__ float g_sk [B_*S_*HD];
__device__ float g_tk [B_*T_*HD];
__device__ float g_sv [B_*S_*HD];
__device__ float g_tv [B_*T_*HD];
__device__ float g_svT[B_*HD*S_];
__device__ float g_tvT[B_*HD*T_];
__device__ float g_w  [(size_t)B_*L_*ST_];       // 33.5 MB
__device__ float g_rs [B_*L_];
__device__ float g_ctx[B_*L_*HD];
__device__ float g_part[128*128*512];            // split-K scratch (33.5 MB)

// ---------------- small helpers ---------------------------------------------
__device__ __forceinline__ u32 tf32r(float x){
    u32 y; asm("cvt.rna.tf32.f32 %0, %1;":"=r"(y):"f"(x)); return y;
}
__device__ __forceinline__ uint4 cvt4(float4 v){
    uint4 o; o.x=tf32r(v.x); o.y=tf32r(v.y); o.z=tf32r(v.z); o.w=tf32r(v.w); return o;
}
__device__ __forceinline__ void mma8(float d[4], const u32 a[4], const u32 b[2]){
    asm volatile("mma.sync.aligned.m16n8k8.row.col.f32.tf32.tf32.f32 "
        "{%0,%1,%2,%3}, {%4,%5,%6,%7}, {%8,%9}, {%0,%1,%2,%3};"
        : "+f"(d[0]),"+f"(d[1]),"+f"(d[2]),"+f"(d[3])
        : "r"(a[0]),"r"(a[1]),"r"(a[2]),"r"(a[3]),"r"(b[0]),"r"(b[1]));
}

// dynamic smem (floats): A slots @ 0,4096 ; B slots @ 8192,12288  (64 KB total)
#define SMEM_MMA 65536

// ============ trilinear logits via mma.sync: C[128l x 128st] = Q @ P^T ======
// P[st,k] = sk[s,k]*tk[t,k] built in SMEM per 32-wide K chunk.  K = 512.
__global__ __launch_bounds__(256) void tri_mma(const float* __restrict__ q,
        const float* __restrict__ sk, const float* __restrict__ tk, float* __restrict__ w){
    extern __shared__ __align__(16) float dsm[];
    int tid=threadIdx.x, lane=tid&31, wid=tid>>5;
    int wm = wid&3, wn = wid>>2;
    int gid = lane>>2, tig = lane&3;
    int tile = blockIdx.x, b = blockIdx.y;
    const float* qb  = q  + (size_t)b*L_*HD;
    const float* skb = sk + (size_t)b*S_*HD;
    const float* tkb = tk + (size_t)b*T_*HD;

    // staging coords: 4 float4 per thread per tile
    int row_[4], seg_[4];
    #pragma unroll
    for (int j=0;j<4;j++){ int f4 = tid + j*256; row_[j]=f4>>3; seg_[j]=f4&7; }

    float acc[2][8][4];
    #pragma unroll
    for(int mf=0;mf<2;mf++)
        #pragma unroll
        for(int nf=0;nf<8;nf++)
            #pragma unroll
            for(int r=0;r<4;r++) acc[mf][nf][r]=0.f;

    uint4 pa[4], pb[4];
    // prefetch k-tile 0
    #pragma unroll
    for (int j=0;j<4;j++){
        pa[j] = cvt4(*(const float4*)(qb + (size_t)row_[j]*HD + seg_[j]*4));
        int st = tile*128 + row_[j], s = st>>6, t = st&63;
        float4 a = *(const float4*)(tkb + (size_t)t*HD + seg_[j]*4);
        float4 c = *(const float4*)(skb + (size_t)s*HD + seg_[j]*4);
        pb[j] = cvt4(make_float4(a.x*c.x, a.y*c.y, a.z*c.z, a.w*c.w));
    }
    {   uint4* A4 = (uint4*)dsm; uint4* B4 = (uint4*)(dsm + 8192);
        #pragma unroll
        for (int j=0;j<4;j++){
            A4[row_[j]*8 + (seg_[j]^(row_[j]&7))] = pa[j];
            B4[row_[j]*8 + (seg_[j]^(row_[j]&7))] = pb[j];
        }
    }
    __syncthreads();

    const int NT = HD/32;   // 16
    int k00 = tig ^ (gid<<2);
    for (int kt=0; kt<NT; kt++){
        int slot = kt&1;
        if (kt+1 < NT){
            int kc = (kt+1)*32;
            #pragma unroll
            for (int j=0;j<4;j++){
                pa[j] = cvt4(*(const float4*)(qb + (size_t)row_[j]*HD + kc + seg_[j]*4));
                int st = tile*128 + row_[j], s = st>>6, t = st&63;
                float4 a = *(const float4*)(tkb + (size_t)t*HD + kc + seg_[j]*4);
                float4 c = *(const float4*)(skb + (size_t)s*HD + kc + seg_[j]*4);
                pb[j] = cvt4(make_float4(a.x*c.x, a.y*c.y, a.z*c.z, a.w*c.w));
            }
        }
        const u32* As = (const u32*)dsm + slot*4096;
        const u32* Bs = (const u32*)dsm + 8192 + slot*4096;
        #pragma unroll
        for (int ks=0; ks<4; ks++){
            int kk0 = k00 ^ (ks<<3), kk1 = kk0 ^ 4;
            u32 afr[2][4];
            #pragma unroll
            for (int mf=0;mf<2;mf++){
                int rb = (wm*32 + mf*16 + gid)*32;
                afr[mf][0]=As[rb+kk0];     afr[mf][1]=As[rb+256+kk0];
                afr[mf][2]=As[rb+kk1];     afr[mf][3]=As[rb+256+kk1];
            }
            u32 bfr[8][2];
            #pragma unroll
            for (int nf=0;nf<8;nf++){
                int rb = (wn*64 + nf*8 + gid)*32;
                bfr[nf][0]=Bs[rb+kk0];     bfr[nf][1]=Bs[rb+kk1];
            }
            #pragma unroll
            for (int mf=0;mf<2;mf++)
                #pragma unroll
                for (int nf=0;nf<8;nf++) mma8(acc[mf][nf], afr[mf], bfr[nf]);
        }
        if (kt+1 < NT){
            int nxt = slot^1;
            uint4* A4 = (uint4*)(dsm + nxt*4096);
            uint4* B4 = (uint4*)(dsm + 8192 + nxt*4096);
            #pragma unroll
            for (int j=0;j<4;j++){
                A4[row_[j]*8 + (seg_[j]^(row_[j]&7))] = pa[j];
                B4[row_[j]*8 + (seg_[j]^(row_[j]&7))] = pb[j];
            }
        }
        __syncthreads();
    }

    const float scale = 0.044194173824159216f;  // 1/sqrt(512)
    #pragma unroll
    for (int mf=0;mf<2;mf++){
        int row = wm*32 + mf*16 + gid;
        float* w0 = w + ((size_t)(b*L_+row))*ST_ + tile*128 + wn*64 + tig*2;
        #pragma unroll
        for (int nf=0;nf<8;nf++){
            *(float2*)(w0 + nf*8)          = make_float2(acc[mf][nf][0]*scale, acc[mf][nf][1]*scale);
            *(float2*)(w0 + nf*8 + 8*ST_)  = make_float2(acc[mf][nf][2]*scale, acc[mf][nf][3]*scale);
        }
    }
}

// ====== ctx via mma.sync: part[b,sp][128l x 128k] = E_chunk @ V^T ===========
// V[k_out, st] = svT[k_out,s]*tvT[k_out,t]; split-K over st: 4 x 1024.
__global__ __launch_bounds__(256) void ctx_mma(const float* __restrict__ E,
        const float* __restrict__ svT, const float* __restrict__ tvT, float* __restrict__ part){
    extern __shared__ __align__(16) float dsm[];
    int tid=threadIdx.x, lane=tid&31, wid=tid>>5;
    int wm = wid&3, wn = wid>>2;
    int gid = lane>>2, tig = lane&3;
    int n0 = blockIdx.x*128, sp = blockIdx.y, b = blockIdx.z;
    const float* Eb  = E   + (size_t)b*L_*ST_ + sp*1024;
    const float* svb = svT + ((size_t)b*HD + n0)*S_;
    const float* tvb = tvT + ((size_t)b*HD + n0)*T_;

    int row_[4], seg_[4];
    #pragma unroll
    for (int j=0;j<4;j++){ int f4 = tid + j*256; row_[j]=f4>>3; seg_[j]=f4&7; }

    float acc[2][8][4];
    #pragma unroll
    for(int mf=0;mf<2;mf++)
        #pragma unroll
        for(int nf=0;nf<8;nf++)
            #pragma unroll
            for(int r=0;r<4;r++) acc[mf][nf][r]=0.f;

    uint4 pa[4], pb[4];
    {   int st0 = sp*1024, s = st0>>6, tb = st0&63;
        #pragma unroll
        for (int j=0;j<4;j++){
            pa[j] = cvt4(*(const float4*)(Eb + (size_t)row_[j]*ST_ + seg_[j]*4));
            float4 t4 = *(const float4*)(tvb + (size_t)row_[j]*T_ + tb + seg_[j]*4);
            float sc = svb[(size_t)row_[j]*S_ + s];
            pb[j] = cvt4(make_float4(t4.x*sc, t4.y*sc, t4.z*sc, t4.w*sc));
        }
    }
    {   uint4* A4 = (uint4*)dsm; uint4* B4 = (uint4*)(dsm + 8192);
        #pragma unroll
        for (int j=0;j<4;j++){
            A4[row_[j]*8 + (seg_[j]^(row_[j]&7))] = pa[j];
            B4[row_[j]*8 + (seg_[j]^(row_[j]&7))] = pb[j];
        }
    }
    __syncthreads();

    const int NT = 1024/32;  // 32
    int k00 = tig ^ (gid<<2);
    for (int kt=0; kt<NT; kt++){
        int slot = kt&1;
        if (kt+1 < NT){
            int kc = (kt+1)*32;
            int st0 = sp*1024 + kc, s = st0>>6, tb = st0&63;
            #pragma unroll
            for (int j=0;j<4;j++){
                pa[j] = cvt4(*(const float4*)(Eb + (size_t)row_[j]*ST_ + kc + seg_[j]*4));
                float4 t4 = *(const float4*)(tvb + (size_t)row_[j]*T_ + tb + seg_[j]*4);
                float sc = svb[(size_t)row_[j]*S_ + s];
                pb[j] = cvt4(make_float4(t4.x*sc, t4.y*sc, t4.z*sc, t4.w*sc));
            }
        }
        const u32* As = (const u32*)dsm + slot*4096;
        const u32* Bs = (const u32*)dsm + 8192 + slot*4096;
        #pragma unroll
        for (int ks=0; ks<4; ks++){
            int kk0 = k00 ^ (ks<<3), kk1 = kk0 ^ 4;
            u32 afr[2][4];
            #pragma unroll
            for (int mf=0;mf<2;mf++){
                int rb = (wm*32 + mf*16 + gid)*32;
                afr[mf][0]=As[rb+kk0];     afr[mf][1]=As[rb+256+kk0];
                afr[mf][2]=As[rb+kk1];     afr[mf][3]=As[rb+256+kk1];
            }
            u32 bfr[8][2];
            #pragma unroll
            for (int nf=0;nf<8;nf++){
                int rb = (wn*64 + nf*8 + gid)*32;
                bfr[nf][0]=Bs[rb+kk0];     bfr[nf][1]=Bs[rb+kk1];
            }
            #pragma unroll
            for (int mf=0;mf<2;mf++)
                #pragma unroll
                for (int nf=0;nf<8;nf++) mma8(acc[mf][nf], afr[mf], bfr[nf]);
        }
        if (kt+1 < NT){
            int nxt = slot^1;
            uint4* A4 = (uint4*)(dsm + nxt*4096);
            uint4* B4 = (uint4*)(dsm + 8192 + nxt*4096);
            #pragma unroll
            for (int j=0;j<4;j++){
                A4[row_[j]*8 + (seg_[j]^(row_[j]&7))] = pa[j];
                B4[row_[j]*8 + (seg_[j]^(row_[j]&7))] = pb[j];
            }
        }
        __syncthreads();
    }

    #pragma unroll
    for (int mf=0;mf<2;mf++){
        int row = wm*32 + mf*16 + gid;
        float* p0 = part + ((size_t)(b*4+sp)*128 + row)*512 + n0 + wn*64 + tig*2;
        #pragma unroll
        for (int nf=0;nf<8;nf++){
            *(float2*)(p0 + nf*8)         = make_float2(acc[mf][nf][0], acc[mf][nf][1]);
            *(float2*)(p0 + nf*8 + 8*512) = make_float2(acc[mf][nf][2], acc[mf][nf][3]);
        }
    }
}

// -------- transpose sv/tv: vT[b][k][s] = v[b][s][k] ------------------------
__global__ void transpose_vals(const float* __restrict__ sv, const float* __restrict__ tv,
                               float* __restrict__ svT, float* __restrict__ tvT){
    __shared__ float tilebuf[64][65];
    int k0 = blockIdx.x*64, b = blockIdx.y;
    const float* src = blockIdx.z ? tv : sv;
    float* dst = blockIdx.z ? tvT : svT;
    int tid = threadIdx.x;
    #pragma unroll
    for (int j = 0; j < 16; j++){
        int e = tid + j*256, s = e>>6, k = e&63;
        tilebuf[k][s] = src[(size_t)(b*64 + s)*HD + k0 + k];
    }
    __syncthreads();
    #pragma unroll
    for (int j = 0; j < 16; j++){
        int e = tid + j*256, k = e>>6, s = e&63;
        dst[(size_t)(b*HD + k0 + k)*64 + s] = tilebuf[k][s];
    }
}

// ---------------- packed f32x2 helpers (SIMT kernels) -----------------------
__device__ __forceinline__ u64 pk2(float x, float y){
    u64 r; asm("mov.b64 %0,{%1,%2};":"=l"(r):"f"(x),"f"(y)); return r;
}
__device__ __forceinline__ void fma2(u64 &c, u64 a, u64 b){
    asm("fma.rn.f32x2 %0,%1,%2,%0;":"+l"(c):"l"(a),"l"(b));
}
__device__ __forceinline__ float2 upk2(u64 v){
    float lo,hi; asm("mov.b64 {%0,%1},%2;":"=f"(lo),"=f"(hi):"l"(v));
    return make_float2(lo,hi);
}
__device__ __forceinline__ void mma_step(u64 acc[8][4], float4 a0, float4 a1, const u64 bp[4]){
    u64 ad[8];
    ad[0]=pk2(a0.x,a0.x); ad[1]=pk2(a0.y,a0.y); ad[2]=pk2(a0.z,a0.z); ad[3]=pk2(a0.w,a0.w);
    ad[4]=pk2(a1.x,a1.x); ad[5]=pk2(a1.y,a1.y); ad[6]=pk2(a1.z,a1.z); ad[7]=pk2(a1.w,a1.w);
    #pragma unroll
    for (int i=0;i<8;i++)
        #pragma unroll
        for (int p=0;p<4;p++) fma2(acc[i][p], ad[i], bp[p]);
}

// ======================= merged projection GEMMs ============================
struct ProjArgs {
    const float* A[5];
    const float* W[5];
    const float* bias[5];
    float*       C[5];
};

__global__ __launch_bounds__(256,2) void proj_kernel(ProjArgs args){
    __shared__ __align__(16) float As[2][8][128];
    __shared__ __align__(16) float Bs[2][8][128];
    int tid = threadIdx.x, tx = tid&15, ty = tid>>4;
    int y = blockIdx.y;
    int task, mt;
    if (y < 16){ task=0; mt=y; } else { task = 1 + ((y-16)>>3); mt = (y-16)&7; }
    const float* A    = args.A[task];
    const float* Wm   = args.W[task];
    const float* bias = args.bias[task];
    float*       C    = args.C[task];
    int bm = mt*128, bn = blockIdx.x*128;
    const int K = 1024;

    int ar = tid>>1, akc = (tid&1)*4;
    int br = tid>>5, bc = (tid&31)*4;
    const float* Ap = A  + (size_t)(bm+ar)*K + akc;
    const float* Bp = Wm + (size_t)br*OD + bn + bc;

    float4 ra = *(const float4*)Ap;
    float4 rb = *(const float4*)Bp;
    {   float av[4]={ra.x,ra.y,ra.z,ra.w};
        #pragma unroll
        for(int i=0;i<4;i++){ int k=akc+i; As[0][k][ar ^ (k<<2)] = av[i]; }
        *(float4*)&Bs[0][br][bc] = rb;
    }
    __syncthreads();

    u64 acc[8][4];
    #pragma unroll
    for(int i=0;i<8;i++)
        #pragma unroll
        for(int p=0;p<4;p++) acc[i][p]=0ull;

    const int ntk = K/8;
    for (int kt=0; kt<ntk; kt++){
        int cur = kt&1;
        if (kt+1 < ntk){
            ra = *(const float4*)(Ap + (kt+1)*8);
            rb = *(const float4*)(Bp + (size_t)(kt+1)*8*OD);
        }
        #pragma unroll
        for (int k=0;k<8;k++){
            int sc = k<<2;
            float4 a0 = *(const float4*)&As[cur][k][(ty*4)^sc];
            float4 a1 = *(const float4*)&As[cur][k][(64+ty*4)^sc];
            ulonglong2 b0 = *(const ulonglong2*)&Bs[cur][k][tx*4];
            ulonglong2 b1 = *(const ulonglong2*)&Bs[cur][k][64+tx*4];
            u64 bp[4] = { b0.x, b0.y, b1.x, b1.y };
            mma_step(acc, a0, a1, bp);
        }
        if (kt+1 < ntk){
            int nxt = cur^1;
            float av[4]={ra.x,ra.y,ra.z,ra.w};
            #pragma unroll
            for(int i=0;i<4;i++){ int k=akc+i; As[nxt][k][ar ^ (k<<2)] = av[i]; }
            *(float4*)&Bs[nxt][br][bc] = rb;
        }
        __syncthreads();
    }
    #pragma unroll
    for (int i=0;i<8;i++){
        int m = bm + ((i<4)? ty*4+i : 64+ty*4+(i-4));
        #pragma unroll
        for (int h=0; h<2; h++){
            int n = bn + h*64 + tx*4;
            float2 u0 = upk2(acc[i][h*2+0]);
            float2 u1 = upk2(acc[i][h*2+1]);
            float4 o = make_float4(u0.x+bias[n], u0.y+bias[n+1], u1.x+bias[n+2], u1.y+bias[n+3]);
            *(float4*)(C + (size_t)m*OD + n) = o;
        }
    }
}

// ----------- joint softmax over st=4096; stores exp in place + rowsum -------
__global__ void softmax_kernel(float* __restrict__ w, float* __restrict__ rowsum) {
    int row = blockIdx.x;
    float4* p4 = (float4*)(w + (size_t)row * ST_);
    int tid = threadIdx.x;
    float4 v[4];
    float mx = -1e30f;
    #pragma unroll
    for (int i = 0; i < 4; i++) {
        v[i] = p4[tid + i*256];
        mx = fmaxf(mx, fmaxf(fmaxf(v[i].x, v[i].y), fmaxf(v[i].z, v[i].w)));
    }
    __shared__ float red[256];
    red[tid] = mx; __syncthreads();
    #pragma unroll
    for (int s = 128; s > 0; s >>= 1) {
        if (tid < s) red[tid] = fmaxf(red[tid], red[tid+s]);
        __syncthreads();
    }
    mx = red[0];
    __syncthreads();
    float sum = 0.f;
    #pragma unroll
    for (int i = 0; i < 4; i++) {
        float4 e;
        e.x = expf(v[i].x - mx); e.y = expf(v[i].y - mx);
        e.z = expf(v[i].z - mx); e.w = expf(v[i].w - mx);
        sum += (e.x + e.y) + (e.z + e.w);
        p4[tid + i*256] = e;
    }
    red[tid] = sum; __syncthreads();
    #pragma unroll
    for (int s = 128; s > 0; s >>= 1) {
        if (tid < s) red[tid] += red[tid+s];
        __syncthreads();
    }
    if (tid == 0) rowsum[row] = red[0];
}

// reduce the 4 split-K partials, apply 1/rowsum
__global__ void ctx_reduce(const float* __restrict__ part, const float* __restrict__ rs,
                           float* __restrict__ ctx){
    int gid = blockIdx.x*256 + threadIdx.x;       // float4 id over 16*128*128
    int n4 = gid & 127; int rest = gid >> 7; int l = rest & 127; int b = rest >> 7;
    const float4* p = (const float4*)part;
    float4 a = make_float4(0,0,0,0);
    #pragma unroll
    for (int sp=0; sp<4; sp++){
        float4 v = p[ ((size_t)(b*4+sp)*128 + l)*128 + n4 ];
        a.x+=v.x; a.y+=v.y; a.z+=v.z; a.w+=v.w;
    }
    float inv = 1.f / rs[b*128 + l];
    ((float4*)ctx)[gid] = make_float4(a.x*inv, a.y*inv, a.z*inv, a.w*inv);
}

// ===== out partial: part[sp, m, n] = concat(query,ctx)[m, k-range] @ Wo =====
__global__ __launch_bounds__(256,2) void out_kernel(const float* __restrict__ query,
        const float* __restrict__ ctx, const float* __restrict__ Wo, float* __restrict__ part){
    __shared__ __align__(16) float As[2][8][128];
    __shared__ __align__(16) float Bs[2][8][128];
    int tid=threadIdx.x, tx=tid&15, ty=tid>>4;
    int bm = blockIdx.y*128, bn = blockIdx.x*128;
    int sp = blockIdx.z; int k_base = sp*768;
    int ar=tid>>1, akc=(tid&1)*4;
    int br=tid>>5, bc=(tid&31)*4;

    float4 ra, rb;
    {   int k = k_base + akc;
        ra = (k < 1024) ? *(const float4*)(query + (size_t)(bm+ar)*QD + k)
                        : *(const float4*)(ctx   + (size_t)(bm+ar)*HD + (k-1024));
        rb = *(const float4*)(Wo + (size_t)(k_base+br)*OD + bn + bc);
    }
    {   float av[4]={ra.x,ra.y,ra.z,ra.w};
        #pragma unroll
        for(int i=0;i<4;i++){ int k=akc+i; As[0][k][ar ^ (k<<2)] = av[i]; }
        *(float4*)&Bs[0][br][bc] = rb;
    }
    __syncthreads();

    u64 acc[8][4];
    #pragma unroll
    for(int i=0;i<8;i++)
        #pragma unroll
        for(int p=0;p<4;p++) acc[i][p]=0ull;

    const int ntk = 768/8;
    for (int kt=0; kt<ntk; kt++){
        int cur = kt&1;
        if (kt+1 < ntk){
            int k = k_base + (kt+1)*8 + akc;
            ra = (k < 1024) ? *(const float4*)(query + (size_t)(bm+ar)*QD + k)
                            : *(const float4*)(ctx   + (size_t)(bm+ar)*HD + (k-1024));
            rb = *(const float4*)(Wo + (size_t)(k_base+(kt+1)*8+br)*OD + bn + bc);
        }
        #pragma unroll
        for (int k=0;k<8;k++){
            int sc = k<<2;
            float4 a0 = *(const float4*)&As[cur][k][(ty*4)^sc];
            float4 a1 = *(const float4*)&As[cur][k][(64+ty*4)^sc];
            ulonglong2 b0 = *(const ulonglong2*)&Bs[cur][k][tx*4];
            ulonglong2 b1 = *(const ulonglong2*)&Bs[cur][k][64+tx*4];
            u64 bp[4] = { b0.x, b0.y, b1.x, b1.y };
            mma_step(acc, a0, a1, bp);
        }
        if (kt+1 < ntk){
            int nxt = cur^1;
            float av[4]={ra.x,ra.y,ra.z,ra.w};
            #pragma unroll
            for(int i=0;i<4;i++){ int k=akc+i; As[nxt][k][ar ^ (k<<2)] = av[i]; }
            *(float4*)&Bs[nxt][br][bc] = rb;
        }
        __syncthreads();
    }
    #pragma unroll
    for (int i=0;i<8;i++){
        int m = bm + ((i<4)? ty*4+i : 64+ty*4+(i-4));
        #pragma unroll
        for (int h=0; h<2; h++){
            float2 u0 = upk2(acc[i][h*2+0]);
            float2 u1 = upk2(acc[i][h*2+1]);
            float4 o = make_float4(u0.x, u0.y, u1.x, u1.y);
            *(float4*)(part + ((size_t)sp*2048 + m)*512 + bn + h*64 + tx*4) = o;
        }
    }
}

// reduce 2 split-K partials + bias + relu
__global__ void out_reduce(const float* __restrict__ part, const float* __restrict__ bo,
                           float* __restrict__ out){
    int gid = blockIdx.x*256 + threadIdx.x;
    int n4 = gid & 127; int m = gid >> 7;
    float4 p0 = ((const float4*)part)[(size_t)m*128 + n4];
    float4 p1 = ((const float4*)part)[(size_t)(2048+m)*128 + n4];
    float4 bb = ((const float4*)bo)[n4];
    float4 o = make_float4(fmaxf(p0.x+p1.x+bb.x, 0.f), fmaxf(p0.y+p1.y+bb.y, 0.f),
                           fmaxf(p0.z+p1.z+bb.z, 0.f), fmaxf(p0.w+p1.w+bb.w, 0.f));
    ((float4*)out)[gid] = o;
}

// ----------------------------------------------------------------------------
extern "C" void kernel_launch(void* const* d_in, const int* in_sizes, int n_in,
                              void* d_out, int out_size) {
    const float* query = (const float*)d_in[0];
    const float* src   = (const float*)d_in[1];
    const float* trg   = (const float*)d_in[2];
    const float* Wq    = (const float*)d_in[3];
    const float* bq    = (const float*)d_in[4];
    const float* Ws    = (const float*)d_in[5];
    const float* bs    = (const float*)d_in[6];
    const float* Wt    = (const float*)d_in[7];
    const float* bt    = (const float*)d_in[8];
    const float* Wsv   = (const float*)d_in[9];
    const float* bsv   = (const float*)d_in[10];
    const float* Wtv   = (const float*)d_in[11];
    const float* btv   = (const float*)d_in[12];
    const float* Wo    = (const float*)d_in[13];
    const float* bo    = (const float*)d_in[14];
    float* out = (float*)d_out;

    float *gq, *gsk, *gtk, *gsv, *gtv, *gsvT, *gtvT, *gw, *grs, *gctx, *gpart;
    cudaGetSymbolAddress((void**)&gq,   g_q);
    cudaGetSymbolAddress((void**)&gsk,  g_sk);
    cudaGetSymbolAddress((void**)&gtk,  g_tk);
    cudaGetSymbolAddress((void**)&gsv,  g_sv);
    cudaGetSymbolAddress((void**)&gtv,  g_tv);
    cudaGetSymbolAddress((void**)&gsvT, g_svT);
    cudaGetSymbolAddress((void**)&gtvT, g_tvT);
    cudaGetSymbolAddress((void**)&gw,   g_w);
    cudaGetSymbolAddress((void**)&grs,  g_rs);
    cudaGetSymbolAddress((void**)&gctx, g_ctx);
    cudaGetSymbolAddress((void**)&gpart,g_part);

    static int smem_set = 0;
    if (!smem_set){
        cudaFuncSetAttribute(tri_mma, cudaFuncAttributeMaxDynamicSharedMemorySize, SMEM_MMA);
        cudaFuncSetAttribute(ctx_mma, cudaFuncAttributeMaxDynamicSharedMemorySize, SMEM_MMA);
        smem_set = 1;
    }

    ProjArgs pa;
    pa.A[0]=query; pa.A[1]=src; pa.A[2]=trg; pa.A[3]=src; pa.A[4]=trg;
    pa.W[0]=Wq;    pa.W[1]=Ws;  pa.W[2]=Wt;  pa.W[3]=Wsv; pa.W[4]=Wtv;
    pa.bias[0]=bq; pa.bias[1]=bs; pa.bias[2]=bt; pa.bias[3]=bsv; pa.bias[4]=btv;
    pa.C[0]=gq;    pa.C[1]=gsk; pa.C[2]=gtk; pa.C[3]=gsv; pa.C[4]=gtv;

    proj_kernel   <<<dim3(4,48),    256>>>(pa);
    transpose_vals<<<dim3(8,16,2),  256>>>(gsv, gtv, gsvT, gtvT);
    tri_mma       <<<dim3(32,16),   256, SMEM_MMA>>>(gq, gsk, gtk, gw);
    softmax_kernel<<<B_*L_,         256>>>(gw, grs);
    ctx_mma       <<<dim3(4,4,16),  256, SMEM_MMA>>>(gw, gsvT, gtvT, gpart);
    ctx_reduce    <<<1024,          256>>>(gpart, grs, gctx);
    out_kernel    <<<dim3(4,16,2),  256>>>(query, gctx, Wo, gpart);
    out_reduce    <<<1024,          256>>>(gpart, bo, out);
}

// round 5
// speedup vs baseline: 3.1282x; 1.4084x over previous
#include <cuda_runtime.h>
#include <math.h>

#define B_  16
#define L_  128
#define S_  64
#define T_  64
#define QD  1024
#define HD  512
#define OD  512
#define ST_ 4096

typedef unsigned long long u64;
typedef unsigned int u32;

// ---------------- scratch (static device globals) ---------------------------
__device__ float g_q  [B_*L_*HD];
__device__ float g_sk [B_*S_*HD];
__device__ float g_tk [B_*T_*HD];
__device__ float g_sv [B_*S_*HD];
__device__ float g_tv [B_*T_*HD];
__device__ float g_svT[B_*HD*S_];
__device__ float g_tvT[B_*HD*T_];
__device__ float g_w  [(size_t)B_*L_*ST_];       // 33.5 MB
__device__ float g_rs [B_*L_];
__device__ float g_ctx[B_*L_*HD];
__device__ float g_part[128*128*512];            // split-K scratch (33.5 MB)
__device__ float g_wT [5*512*1024 + 512*1536];   // transposed weights (13.6 MB)

// ---------------- small helpers ---------------------------------------------
__device__ __forceinline__ u32 tf32r(float x){
    u32 y; asm("cvt.rna.tf32.f32 %0, %1;":"=r"(y):"f"(x)); return y;
}
__device__ __forceinline__ uint4 cvt4(float4 v){
    uint4 o; o.x=tf32r(v.x); o.y=tf32r(v.y); o.z=tf32r(v.z); o.w=tf32r(v.w); return o;
}
__device__ __forceinline__ void mma8(float d[4], const u32 a[4], const u32 b[2]){
    asm volatile("mma.sync.aligned.m16n8k8.row.col.f32.tf32.tf32.f32 "
        "{%0,%1,%2,%3}, {%4,%5,%6,%7}, {%8,%9}, {%0,%1,%2,%3};"
        : "+f"(d[0]),"+f"(d[1]),"+f"(d[2]),"+f"(d[3])
        : "r"(a[0]),"r"(a[1]),"r"(a[2]),"r"(a[3]),"r"(b[0]),"r"(b[1]));
}

// dynamic smem (floats): A slots @ 0,4096 ; B slots @ 8192,12288  (64 KB total)
#define SMEM_MMA 65536

// ---- shared mma-tile core pieces (macros keep register allocation tight) ----
#define MMA_PROLOG() \
    int tid=threadIdx.x, lane=tid&31, wid=tid>>5; \
    int wm = wid&3, wn = wid>>2; \
    int gid = lane>>2, tig = lane&3; \
    int row_[4], seg_[4]; \
    _Pragma("unroll") \
    for (int j=0;j<4;j++){ int f4 = tid + j*256; row_[j]=f4>>3; seg_[j]=f4&7; } \
    float acc[2][8][4]; \
    _Pragma("unroll") \
    for(int mf=0;mf<2;mf++) \
        _Pragma("unroll") \
        for(int nf=0;nf<8;nf++) \
            _Pragma("unroll") \
            for(int r=0;r<4;r++) acc[mf][nf][r]=0.f; \
    uint4 pa[4], pb[4];

#define MMA_STORE_STAGE(slotbase) do { \
    uint4* A4 = (uint4*)(dsm + (slotbase)); \
    uint4* B4 = (uint4*)(dsm + 8192 + (slotbase)); \
    _Pragma("unroll") \
    for (int j=0;j<4;j++){ \
        A4[row_[j]*8 + (seg_[j]^(row_[j]&7))] = pa[j]; \
        B4[row_[j]*8 + (seg_[j]^(row_[j]&7))] = pb[j]; \
    } \
} while(0)

#define MMA_COMPUTE(slot) do { \
    const u32* As = (const u32*)dsm + (slot)*4096; \
    const u32* Bs = (const u32*)dsm + 8192 + (slot)*4096; \
    int k00 = tig ^ (gid<<2); \
    _Pragma("unroll") \
    for (int ks=0; ks<4; ks++){ \
        int kk0 = k00 ^ (ks<<3), kk1 = kk0 ^ 4; \
        u32 afr[2][4]; \
        _Pragma("unroll") \
        for (int mf=0;mf<2;mf++){ \
            int rb = (wm*32 + mf*16 + gid)*32; \
            afr[mf][0]=As[rb+kk0];     afr[mf][1]=As[rb+256+kk0]; \
            afr[mf][2]=As[rb+kk1];     afr[mf][3]=As[rb+256+kk1]; \
        } \
        u32 bfr[8][2]; \
        _Pragma("unroll") \
        for (int nf=0;nf<8;nf++){ \
            int rb = (wn*64 + nf*8 + gid)*32; \
            bfr[nf][0]=Bs[rb+kk0];     bfr[nf][1]=Bs[rb+kk1]; \
        } \
        _Pragma("unroll") \
        for (int mf=0;mf<2;mf++) \
            _Pragma("unroll") \
            for (int nf=0;nf<8;nf++) mma8(acc[mf][nf], afr[mf], bfr[nf]); \
    } \
} while(0)

// ============ trilinear logits via mma.sync: C[128l x 128st] = Q @ P^T ======
__global__ __launch_bounds__(256) void tri_mma(const float* __restrict__ q,
        const float* __restrict__ sk, const float* __restrict__ tk, float* __restrict__ w){
    extern __shared__ __align__(16) float dsm[];
    int tile = blockIdx.x, b = blockIdx.y;
    const float* qb  = q  + (size_t)b*L_*HD;
    const float* skb = sk + (size_t)b*S_*HD;
    const float* tkb = tk + (size_t)b*T_*HD;
    MMA_PROLOG();

    #pragma unroll
    for (int j=0;j<4;j++){
        pa[j] = cvt4(*(const float4*)(qb + (size_t)row_[j]*HD + seg_[j]*4));
        int st = tile*128 + row_[j], s = st>>6, t = st&63;
        float4 a = *(const float4*)(tkb + (size_t)t*HD + seg_[j]*4);
        float4 c = *(const float4*)(skb + (size_t)s*HD + seg_[j]*4);
        pb[j] = cvt4(make_float4(a.x*c.x, a.y*c.y, a.z*c.z, a.w*c.w));
    }
    MMA_STORE_STAGE(0);
    __syncthreads();

    const int NT = HD/32;   // 16
    for (int kt=0; kt<NT; kt++){
        int slot = kt&1;
        if (kt+1 < NT){
            int kc = (kt+1)*32;
            #pragma unroll
            for (int j=0;j<4;j++){
                pa[j] = cvt4(*(const float4*)(qb + (size_t)row_[j]*HD + kc + seg_[j]*4));
                int st = tile*128 + row_[j], s = st>>6, t = st&63;
                float4 a = *(const float4*)(tkb + (size_t)t*HD + kc + seg_[j]*4);
                float4 c = *(const float4*)(skb + (size_t)s*HD + kc + seg_[j]*4);
                pb[j] = cvt4(make_float4(a.x*c.x, a.y*c.y, a.z*c.z, a.w*c.w));
            }
        }
        MMA_COMPUTE(slot);
        if (kt+1 < NT) MMA_STORE_STAGE((slot^1)*4096);
        __syncthreads();
    }

    const float scale = 0.044194173824159216f;  // 1/sqrt(512)
    #pragma unroll
    for (int mf=0;mf<2;mf++){
        int row = wm*32 + mf*16 + gid;
        float* w0 = w + ((size_t)(b*L_+row))*ST_ + tile*128 + wn*64 + tig*2;
        #pragma unroll
        for (int nf=0;nf<8;nf++){
            *(float2*)(w0 + nf*8)          = make_float2(acc[mf][nf][0]*scale, acc[mf][nf][1]*scale);
            *(float2*)(w0 + nf*8 + 8*ST_)  = make_float2(acc[mf][nf][2]*scale, acc[mf][nf][3]*scale);
        }
    }
}

// ====== ctx via mma.sync: part[b,sp][128l x 128k] = E_chunk @ V^T ===========
__global__ __launch_bounds__(256) void ctx_mma(const float* __restrict__ E,
        const float* __restrict__ svT, const float* __restrict__ tvT, float* __restrict__ part){
    extern __shared__ __align__(16) float dsm[];
    int n0 = blockIdx.x*128, sp = blockIdx.y, b = blockIdx.z;
    const float* Eb  = E   + (size_t)b*L_*ST_ + sp*1024;
    const float* svb = svT + ((size_t)b*HD + n0)*S_;
    const float* tvb = tvT + ((size_t)b*HD + n0)*T_;
    MMA_PROLOG();

    {   int st0 = sp*1024, s = st0>>6, tb = st0&63;
        #pragma unroll
        for (int j=0;j<4;j++){
            pa[j] = cvt4(*(const float4*)(Eb + (size_t)row_[j]*ST_ + seg_[j]*4));
            float4 t4 = *(const float4*)(tvb + (size_t)row_[j]*T_ + tb + seg_[j]*4);
            float sc = svb[(size_t)row_[j]*S_ + s];
            pb[j] = cvt4(make_float4(t4.x*sc, t4.y*sc, t4.z*sc, t4.w*sc));
        }
    }
    MMA_STORE_STAGE(0);
    __syncthreads();

    const int NT = 1024/32;  // 32
    for (int kt=0; kt<NT; kt++){
        int slot = kt&1;
        if (kt+1 < NT){
            int kc = (kt+1)*32;
            int st0 = sp*1024 + kc, s = st0>>6, tb = st0&63;
            #pragma unroll
            for (int j=0;j<4;j++){
                pa[j] = cvt4(*(const float4*)(Eb + (size_t)row_[j]*ST_ + kc + seg_[j]*4));
                float4 t4 = *(const float4*)(tvb + (size_t)row_[j]*T_ + tb + seg_[j]*4);
                float sc = svb[(size_t)row_[j]*S_ + s];
                pb[j] = cvt4(make_float4(t4.x*sc, t4.y*sc, t4.z*sc, t4.w*sc));
            }
        }
        MMA_COMPUTE(slot);
        if (kt+1 < NT) MMA_STORE_STAGE((slot^1)*4096);
        __syncthreads();
    }

    #pragma unroll
    for (int mf=0;mf<2;mf++){
        int row = wm*32 + mf*16 + gid;
        float* p0 = part + ((size_t)(b*4+sp)*128 + row)*512 + n0 + wn*64 + tig*2;
        #pragma unroll
        for (int nf=0;nf<8;nf++){
            *(float2*)(p0 + nf*8)         = make_float2(acc[mf][nf][0], acc[mf][nf][1]);
            *(float2*)(p0 + nf*8 + 8*512) = make_float2(acc[mf][nf][2], acc[mf][nf][3]);
        }
    }
}

// ============ projections via mma.sync: C = A[Mx1024] @ W + bias ============
struct ProjArgs {
    const float* A[5];
    const float* WT[5];
    const float* bias[5];
    float*       C[5];
};

__global__ __launch_bounds__(256) void proj_mma(ProjArgs args){
    extern __shared__ __align__(16) float dsm[];
    int y = blockIdx.y;
    int task, mt;
    if (y < 16){ task=0; mt=y; } else { task = 1 + ((y-16)>>3); mt = (y-16)&7; }
    int bm = mt*128, bn = blockIdx.x*128;
    const float* Ab   = args.A[task]  + (size_t)bm*QD;
    const float* Bb   = args.WT[task] + (size_t)bn*QD;
    const float* bias = args.bias[task];
    float*       C    = args.C[task]  + (size_t)bm*OD + bn;
    MMA_PROLOG();

    #pragma unroll
    for (int j=0;j<4;j++){
        pa[j] = cvt4(*(const float4*)(Ab + (size_t)row_[j]*QD + seg_[j]*4));
        pb[j] = cvt4(*(const float4*)(Bb + (size_t)row_[j]*QD + seg_[j]*4));
    }
    MMA_STORE_STAGE(0);
    __syncthreads();

    const int NT = QD/32;  // 32
    for (int kt=0; kt<NT; kt++){
        int slot = kt&1;
        if (kt+1 < NT){
            int kc = (kt+1)*32;
            #pragma unroll
            for (int j=0;j<4;j++){
                pa[j] = cvt4(*(const float4*)(Ab + (size_t)row_[j]*QD + kc + seg_[j]*4));
                pb[j] = cvt4(*(const float4*)(Bb + (size_t)row_[j]*QD + kc + seg_[j]*4));
            }
        }
        MMA_COMPUTE(slot);
        if (kt+1 < NT) MMA_STORE_STAGE((slot^1)*4096);
        __syncthreads();
    }

    const float* bp = bias + bn + wn*64 + tig*2;
    #pragma unroll
    for (int mf=0;mf<2;mf++){
        int row = wm*32 + mf*16 + gid;
        float* c0 = C + (size_t)row*OD + wn*64 + tig*2;
        #pragma unroll
        for (int nf=0;nf<8;nf++){
            float b0 = bp[nf*8], b1 = bp[nf*8+1];
            *(float2*)(c0 + nf*8)        = make_float2(acc[mf][nf][0]+b0, acc[mf][nf][1]+b1);
            *(float2*)(c0 + nf*8 + 8*OD) = make_float2(acc[mf][nf][2]+b0, acc[mf][nf][3]+b1);
        }
    }
}

// ===== out partials via mma.sync: split-K = 3x512 over concat(query,ctx) ====
__global__ __launch_bounds__(256) void out_mma(const float* __restrict__ query,
        const float* __restrict__ ctx, const float* __restrict__ WoT, float* __restrict__ part){
    extern __shared__ __align__(16) float dsm[];
    int bn = blockIdx.x*128, bm = blockIdx.y*128, sp = blockIdx.z;
    const float* Ab; int lda;
    if (sp < 2){ Ab = query + (size_t)bm*QD + sp*512; lda = QD; }
    else       { Ab = ctx   + (size_t)bm*HD;          lda = HD; }
    const float* Bb = WoT + (size_t)bn*1536 + sp*512;
    MMA_PROLOG();

    #pragma unroll
    for (int j=0;j<4;j++){
        pa[j] = cvt4(*(const float4*)(Ab + (size_t)row_[j]*lda + seg_[j]*4));
        pb[j] = cvt4(*(const float4*)(Bb + (size_t)row_[j]*1536 + seg_[j]*4));
    }
    MMA_STORE_STAGE(0);
    __syncthreads();

    const int NT = 512/32;  // 16
    for (int kt=0; kt<NT; kt++){
        int slot = kt&1;
        if (kt+1 < NT){
            int kc = (kt+1)*32;
            #pragma unroll
            for (int j=0;j<4;j++){
                pa[j] = cvt4(*(const float4*)(Ab + (size_t)row_[j]*lda + kc + seg_[j]*4));
                pb[j] = cvt4(*(const float4*)(Bb + (size_t)row_[j]*1536 + kc + seg_[j]*4));
            }
        }
        MMA_COMPUTE(slot);
        if (kt+1 < NT) MMA_STORE_STAGE((slot^1)*4096);
        __syncthreads();
    }

    #pragma unroll
    for (int mf=0;mf<2;mf++){
        int row = wm*32 + mf*16 + gid;
        float* p0 = part + ((size_t)sp*2048 + bm + row)*512 + bn + wn*64 + tig*2;
        #pragma unroll
        for (int nf=0;nf<8;nf++){
            *(float2*)(p0 + nf*8)         = make_float2(acc[mf][nf][0], acc[mf][nf][1]);
            *(float2*)(p0 + nf*8 + 8*512) = make_float2(acc[mf][nf][2], acc[mf][nf][3]);
        }
    }
}

// -------- transpose weights: WT[n][k] = W[k][n]  (N = 512 always) -----------
struct TWArgs { const float* src[6]; float* dst[6]; int K[6]; };
__global__ void transpose_w(TWArgs a){
    __shared__ float tb[64][65];
    int mid = blockIdx.z;
    int K = a.K[mid];
    int k0 = blockIdx.y*64;
    if (k0 >= K) return;
    int n0 = blockIdx.x*64;
    const float* src = a.src[mid];
    float* dst = a.dst[mid];
    int tid = threadIdx.x;
    #pragma unroll
    for (int j=0;j<16;j++){
        int e = tid + j*256, kk = e>>6, nn = e&63;
        tb[nn][kk] = src[(size_t)(k0+kk)*512 + n0+nn];
    }
    __syncthreads();
    #pragma unroll
    for (int j=0;j<16;j++){
        int e = tid + j*256, nn = e>>6, kk = e&63;
        dst[(size_t)(n0+nn)*K + k0+kk] = tb[nn][kk];
    }
}

// -------- transpose sv/tv: vT[b][k][s] = v[b][s][k] ------------------------
__global__ void transpose_vals(const float* __restrict__ sv, const float* __restrict__ tv,
                               float* __restrict__ svT, float* __restrict__ tvT){
    __shared__ float tilebuf[64][65];
    int k0 = blockIdx.x*64, b = blockIdx.y;
    const float* src = blockIdx.z ? tv : sv;
    float* dst = blockIdx.z ? tvT : svT;
    int tid = threadIdx.x;
    #pragma unroll
    for (int j = 0; j < 16; j++){
        int e = tid + j*256, s = e>>6, k = e&63;
        tilebuf[k][s] = src[(size_t)(b*64 + s)*HD + k0 + k];
    }
    __syncthreads();
    #pragma unroll
    for (int j = 0; j < 16; j++){
        int e = tid + j*256, k = e>>6, s = e&63;
        dst[(size_t)(b*HD + k0 + k)*64 + s] = tilebuf[k][s];
    }
}

// ----------- joint softmax over st=4096; stores exp in place + rowsum -------
__global__ void softmax_kernel(float* __restrict__ w, float* __restrict__ rowsum) {
    int row = blockIdx.x;
    float4* p4 = (float4*)(w + (size_t)row * ST_);
    int tid = threadIdx.x;
    float4 v[4];
    float mx = -1e30f;
    #pragma unroll
    for (int i = 0; i < 4; i++) {
        v[i] = p4[tid + i*256];
        mx = fmaxf(mx, fmaxf(fmaxf(v[i].x, v[i].y), fmaxf(v[i].z, v[i].w)));
    }
    __shared__ float red[256];
    red[tid] = mx; __syncthreads();
    #pragma unroll
    for (int s = 128; s > 0; s >>= 1) {
        if (tid < s) red[tid] = fmaxf(red[tid], red[tid+s]);
        __syncthreads();
    }
    mx = red[0];
    __syncthreads();
    float sum = 0.f;
    #pragma unroll
    for (int i = 0; i < 4; i++) {
        float4 e;
        e.x = expf(v[i].x - mx); e.y = expf(v[i].y - mx);
        e.z = expf(v[i].z - mx); e.w = expf(v[i].w - mx);
        sum += (e.x + e.y) + (e.z + e.w);
        p4[tid + i*256] = e;
    }
    red[tid] = sum; __syncthreads();
    #pragma unroll
    for (int s = 128; s > 0; s >>= 1) {
        if (tid < s) red[tid] += red[tid+s];
        __syncthreads();
    }
    if (tid == 0) rowsum[row] = red[0];
}

// reduce the 4 split-K partials, apply 1/rowsum
__global__ void ctx_reduce(const float* __restrict__ part, const float* __restrict__ rs,
                           float* __restrict__ ctx){
    int gid = blockIdx.x*256 + threadIdx.x;       // float4 id over 16*128*128
    int n4 = gid & 127; int rest = gid >> 7; int l = rest & 127; int b = rest >> 7;
    const float4* p = (const float4*)part;
    float4 a = make_float4(0,0,0,0);
    #pragma unroll
    for (int sp=0; sp<4; sp++){
        float4 v = p[ ((size_t)(b*4+sp)*128 + l)*128 + n4 ];
        a.x+=v.x; a.y+=v.y; a.z+=v.z; a.w+=v.w;
    }
    float inv = 1.f / rs[b*128 + l];
    ((float4*)ctx)[gid] = make_float4(a.x*inv, a.y*inv, a.z*inv, a.w*inv);
}

// reduce 3 split-K partials + bias + relu
__global__ void out_reduce(const float* __restrict__ part, const float* __restrict__ bo,
                           float* __restrict__ out){
    int gid = blockIdx.x*256 + threadIdx.x;       // float4 id over 2048*128
    int n4 = gid & 127; int m = gid >> 7;
    float4 p0 = ((const float4*)part)[(size_t)m*128 + n4];
    float4 p1 = ((const float4*)part)[(size_t)(2048+m)*128 + n4];
    float4 p2 = ((const float4*)part)[(size_t)(4096+m)*128 + n4];
    float4 bb = ((const float4*)bo)[n4];
    float4 o = make_float4(fmaxf(p0.x+p1.x+p2.x+bb.x, 0.f), fmaxf(p0.y+p1.y+p2.y+bb.y, 0.f),
                           fmaxf(p0.z+p1.z+p2.z+bb.z, 0.f), fmaxf(p0.w+p1.w+p2.w+bb.w, 0.f));
    ((float4*)out)[gid] = o;
}

// ----------------------------------------------------------------------------
extern "C" void kernel_launch(void* const* d_in, const int* in_sizes, int n_in,
                              void* d_out, int out_size) {
    const float* query = (const float*)d_in[0];
    const float* src   = (const float*)d_in[1];
    const float* trg   = (const float*)d_in[2];
    const float* Wq    = (const float*)d_in[3];
    const float* bq    = (const float*)d_in[4];
    const float* Ws    = (const float*)d_in[5];
    const float* bs    = (const float*)d_in[6];
    const float* Wt    = (const float*)d_in[7];
    const float* bt    = (const float*)d_in[8];
    const float* Wsv   = (const float*)d_in[9];
    const float* bsv   = (const float*)d_in[10];
    const float* Wtv   = (const float*)d_in[11];
    const float* btv   = (const float*)d_in[12];
    const float* Wo    = (const float*)d_in[13];
    const float* bo    = (const float*)d_in[14];
    float* out = (float*)d_out;

    float *gq, *gsk, *gtk, *gsv, *gtv, *gsvT, *gtvT, *gw, *grs, *gctx, *gpart, *gwT;
    cudaGetSymbolAddress((void**)&gq,   g_q);
    cudaGetSymbolAddress((void**)&gsk,  g_sk);
    cudaGetSymbolAddress((void**)&gtk,  g_tk);
    cudaGetSymbolAddress((void**)&gsv,  g_sv);
    cudaGetSymbolAddress((void**)&gtv,  g_tv);
    cudaGetSymbolAddress((void**)&gsvT, g_svT);
    cudaGetSymbolAddress((void**)&gtvT, g_tvT);
    cudaGetSymbolAddress((void**)&gw,   g_w);
    cudaGetSymbolAddress((void**)&grs,  g_rs);
    cudaGetSymbolAddress((void**)&gctx, g_ctx);
    cudaGetSymbolAddress((void**)&gpart,g_part);
    cudaGetSymbolAddress((void**)&gwT,  g_wT);

    static int smem_set = 0;
    if (!smem_set){
        cudaFuncSetAttribute(tri_mma,  cudaFuncAttributeMaxDynamicSharedMemorySize, SMEM_MMA);
        cudaFuncSetAttribute(ctx_mma,  cudaFuncAttributeMaxDynamicSharedMemorySize, SMEM_MMA);
        cudaFuncSetAttribute(proj_mma, cudaFuncAttributeMaxDynamicSharedMemorySize, SMEM_MMA);
        cudaFuncSetAttribute(out_mma,  cudaFuncAttributeMaxDynamicSharedMemorySize, SMEM_MMA);
        smem_set = 1;
    }

    float* WqT  = gwT;
    float* WsT  = gwT + 1*512*1024;
    float* WtT  = gwT + 2*512*1024;
    float* WsvT = gwT + 3*512*1024;
    float* WtvT = gwT + 4*512*1024;
    float* WoT  = gwT + 5*512*1024;

    TWArgs tw;
    tw.src[0]=Wq;  tw.dst[0]=WqT;  tw.K[0]=1024;
    tw.src[1]=Ws;  tw.dst[1]=WsT;  tw.K[1]=1024;
    tw.src[2]=Wt;  tw.dst[2]=WtT;  tw.K[2]=1024;
    tw.src[3]=Wsv; tw.dst[3]=WsvT; tw.K[3]=1024;
    tw.src[4]=Wtv; tw.dst[4]=WtvT; tw.K[4]=1024;
    tw.src[5]=Wo;  tw.dst[5]=WoT;  tw.K[5]=1536;

    ProjArgs pa;
    pa.A[0]=query; pa.A[1]=src;  pa.A[2]=trg;  pa.A[3]=src;   pa.A[4]=trg;
    pa.WT[0]=WqT;  pa.WT[1]=WsT; pa.WT[2]=WtT; pa.WT[3]=WsvT; pa.WT[4]=WtvT;
    pa.bias[0]=bq; pa.bias[1]=bs; pa.bias[2]=bt; pa.bias[3]=bsv; pa.bias[4]=btv;
    pa.C[0]=gq;    pa.C[1]=gsk;  pa.C[2]=gtk;  pa.C[3]=gsv;   pa.C[4]=gtv;

    transpose_w   <<<dim3(8,24,6),  256>>>(tw);
    proj_mma      <<<dim3(4,48),    256, SMEM_MMA>>>(pa);
    transpose_vals<<<dim3(8,16,2),  256>>>(gsv, gtv, gsvT, gtvT);
    tri_mma       <<<dim3(32,16),   256, SMEM_MMA>>>(gq, gsk, gtk, gw);
    softmax_kernel<<<B_*L_,         256>>>(gw, grs);
    ctx_mma       <<<dim3(4,4,16),  256, SMEM_MMA>>>(gw, gsvT, gtvT, gpart);
    ctx_reduce    <<<1024,          256>>>(gpart, grs, gctx);
    out_mma       <<<dim3(4,16,3),  256, SMEM_MMA>>>(query, gctx, WoT, gpart);
    out_reduce    <<<1024,          256>>>(gpart, bo, out);
}